// round 14
// baseline (speedup 1.0000x reference)
#include <cuda_runtime.h>

#define NS   128
#define NT   2048
#define NB   64
#define NTHR 512   // 4 slices (s=tid>>7) x 128 states; tid<128 also combine

// float-index offsets in dynamic smem
#define OFF_RING 0       // 32768: u64 ring[128 slots][128 j] = (v_ins, ref_ins)
#define OFF_PSH  32768   // 256:  [buf][j] exp(alpha - M)
#define OFF_PMAT 33024   // 512:  [s][j] matvec partials
#define OFF_PDUR 33536   // 1024: [buf][s][j] duration tail partials
#define OFF_FRR  34560   // 512:  u64 [buf][j] = (fac, ref_after_step)
#define OFF_WRED 35072   // 8:    [buf][w] per-warp alpha maxes
#define OFF_EFLG 35080   // 2 ints: emergency-rescale generation, by parity
#define OFF_FIN  35084   // 16
#define SMEM_FLOATS 35104  // ~137.1 KB

typedef unsigned long long u64;

__device__ __forceinline__ u64 pk2(float lo, float hi) {
    u64 r;
    asm("mov.b64 %0, {%1, %2};" : "=l"(r)
        : "r"(__float_as_uint(lo)), "r"(__float_as_uint(hi)));
    return r;
}
__device__ __forceinline__ void upk2(u64 v, float& lo, float& hi) {
    unsigned a, b;
    asm("mov.b64 {%0, %1}, %2;" : "=r"(a), "=r"(b) : "l"(v));
    lo = __uint_as_float(a); hi = __uint_as_float(b);
}
__device__ __forceinline__ float lo2(u64 v) { float a, b; upk2(v, a, b); return a; }
__device__ __forceinline__ u64 ffma2(u64 a, u64 b, u64 c) {
    u64 d;
    asm("fma.rn.f32x2 %0, %1, %2, %3;" : "=l"(d) : "l"(a), "l"(b), "l"(c));
    return d;
}
__device__ __forceinline__ u64 fmul2(u64 a, u64 b) {
    u64 d;
    asm("mul.rn.f32x2 %0, %1, %2;" : "=l"(d) : "l"(a), "l"(b));
    return d;
}
__device__ __forceinline__ unsigned f2key(float x) {
    int i = __float_as_int(x);
    return (unsigned)(i ^ ((i >> 31) | 0x80000000));
}
__device__ __forceinline__ float key2f(unsigned k) {
    int i = ((int)k < 0) ? (int)(k ^ 0x80000000u) : (int)(~k);
    return __int_as_float(i);
}

__global__ __launch_bounds__(NTHR, 1)
void hsmm_fwd_kernel(const float* __restrict__ logB,
                     const float* __restrict__ pi,
                     const float* __restrict__ A,
                     const float* __restrict__ D,
                     float* __restrict__ out)
{
    extern __shared__ float sm[];
    u64*   ring64 = (u64*)(sm + OFF_RING);
    float* p_sh   = sm + OFF_PSH;
    float* pmat   = sm + OFF_PMAT;
    float* pdur   = sm + OFF_PDUR;
    u64*   frref  = (u64*)(sm + OFF_FRR);
    float* wred   = sm + OFF_WRED;
    int*   eflg   = (int*)(sm + OFF_EFLG);
    float* fin    = sm + OFF_FIN;

    const int tid  = threadIdx.x;
    const int b    = blockIdx.x;
    const int lane = tid & 31;
    const int w    = tid >> 5;
    const int j    = tid & 127;
    const int s    = tid >> 7;          // slice 0..3

    // ---------- register tables ----------
    u64 awt[16];        // packed exp(A) pairs for matvec slice s
    u64 dwt2[16];       // packed dur taps: (eD[2+32s+k], eD[2+32s+k+16])
    u64 w2[16];         // pair window: slot (tau&15) = (v_tau, v_{tau-16})
    #pragma unroll
    for (int m = 0; m < 16; ++m) {
        int i0 = 32 * s + 2 * m;
        awt[m] = pk2(__expf(A[i0 * NS + j]), __expf(A[(i0 + 1) * NS + j]));
        int cA = 2 + 32 * s + m;
        int cB = cA + 16;
        float wa = (cA < 128) ? __expf(D[j * 128 + cA]) : 0.0f;
        float wb = (cB < 128) ? __expf(D[j * 128 + cB]) : 0.0f;
        dwt2[m] = pk2(wa, wb);
        w2[m] = 0ull;
    }

    // ---------- init smem ----------
    for (int lin = tid; lin < 16384; lin += NTHR) ring64[lin] = 0ull;
    for (int lin = tid; lin < 1024;  lin += NTHR) pdur[lin] = 0.0f;
    if (tid < 128) {
        p_sh[tid] = 0.0f;  p_sh[128 + tid] = 0.0f;
        frref[tid] = pk2(1.0f, 0.0f);
        frref[128 + tid] = pk2(1.0f, 0.0f);
    }
    if (tid < 8) wred[tid] = 0.0f;
    if (tid < 2) eflg[tid] = -7;

    // combine-role scalars (tid<128)
    float alpha = 0.f, cum = 0.f, ref = 0.f, v_prev = 0.f, Mprev = 0.f;
    float lb_cur = 0.f, eD0 = 0.f, eD1 = 0.f;
    const float* lbp = logB + (size_t)b * NT * NS + j;
    if (tid < 128) {
        lb_cur = lbp[0];
        eD0 = __expf(D[j * 128 + 0]);
        eD1 = __expf(D[j * 128 + 1]);
    }
    __syncthreads();

    const u64 Z = 0ull;
    for (int tb = 0; tb < NT / 32; ++tb) {
        #pragma unroll
        for (int p = 0; p < 32; ++p) {
            const int t = (tb << 5) + p;

            // ================= Phase A =================
            // shared prologue: fac/ref from step t-1 (used by combine AND dur)
            float facA, rnA;
            upk2(frref[((t - 1) & 1) * 128 + j], facA, rnA);

            // combine prologue (reads only step t-1 buffers + registers)
            float tail = 0.f, Mnow = 0.f, K = 0.f, base = 0.f, Kp = 0.f;
            if (tid < 128) {
                float tl0 = pdur[(t & 1) * 512 +   0 + j];
                float tl1 = pdur[(t & 1) * 512 + 128 + j];
                float tl2 = pdur[(t & 1) * 512 + 256 + j];
                float tl3 = pdur[(t & 1) * 512 + 384 + j];
                tail = (tl0 + tl1) + (tl2 + tl3);
                float4 wr4 = *(const float4*)(wred + (t & 1) * 4);
                Mnow = fmaxf(fmaxf(wr4.x, wr4.y), fmaxf(wr4.z, wr4.w));
                K = __expf(Mprev - cum - ref);            // scale for v (cum_old)
                cum += lb_cur;                            // cum[t+1]
                base = cum + ref;
                Kp = __expf(fminf(base - Mnow, 85.0f));   // p_sh fast-path scale
            }
            // trans matvec partial (all threads)
            if (t > 0) {
                const float* psc = p_sh + (t & 1) * 128 + 32 * s;
                u64 a0 = Z, a1 = Z, a2 = Z, a3 = Z;
                #pragma unroll
                for (int k = 0; k < 8; ++k) {
                    ulonglong2 pv = *(const ulonglong2*)(psc + 4 * k);   // broadcast
                    if (k & 1) { a2 = ffma2(pv.x, awt[2 * k], a2); a3 = ffma2(pv.y, awt[2 * k + 1], a3); }
                    else       { a0 = ffma2(pv.x, awt[2 * k], a0); a1 = ffma2(pv.y, awt[2 * k + 1], a1); }
                }
                float x0, x1, y0, y1, z0, z1, u0, u1;
                upk2(a0, x0, x1); upk2(a1, y0, y1); upk2(a2, z0, z1); upk2(a3, u0, u1);
                pmat[s * 128 + j] = ((x0 + x1) + (y0 + y1)) + ((z0 + z1) + (u0 + u1));
            }
            __syncthreads();                                   // sync1: pmat ready

            // ================= Phase B ==================================================
            if (tid < 128) {
                float v;
                if (t == 0) {
                    v = __expf(pi[j]);
                } else {
                    float S = (pmat[j] + pmat[128 + j]) + (pmat[256 + j] + pmat[384 + j]);
                    v = S * K;                            // exp(entry_t - cum_t - ref)
                }
                float dot = fmaf(facA, tail, fmaf(eD1, v_prev, eD0 * v));
                p_sh[((t + 1) & 1) * 128 + j] = dot * Kp; // == exp(alpha - Mnow), fast path

                alpha = base + __logf(dot);               // off-critical (feeds wred/output)
                lb_cur = lbp[(size_t)((t + 1 < NT) ? t + 1 : t) * NS];

                bool sched = ((t & 15) == 15);
                bool emerg = (v > 1e13f);
                float ins, fac;
                if (emerg | (sched & (v > 1e-35f))) {
                    float lv = __logf(v);
                    ref += lv; ins = 1.0f; fac = __expf(-lv);
                    if (emerg & !sched) eflg[t & 1] = t;  // benign same-value race
                } else { ins = v; fac = 1.0f; }
                v_prev = ins;
                frref[(t & 1) * 128 + j] = pk2(fac, ref);
                ring64[(t & 127) * 128 + j] = pk2(ins, ref);
                Mprev = Mnow;

                unsigned ku = f2key(alpha), r;
                asm volatile("redux.sync.max.u32 %0, %1, 0xffffffff;" : "=r"(r) : "r"(ku));
                if (lane == 0) wred[((t + 1) & 1) * 4 + w] = key2f(r);
            }

            // ---- dur: 32-tap pair window (16 u64 slots, static indices) ----
            {
                if (t > 0) {
                    bool rs = ((((t - 1) & 15) == 15) || (eflg[(t - 1) & 1] == t - 1));
                    if (rs) {
                        u64 fac2 = pk2(facA, facA);
                        #pragma unroll
                        for (int k = 0; k < 16; ++k) w2[k] = fmul2(w2[k], fac2);
                    }
                }
                const int bslot = (t - 1 - 32 * s) & 127;     // v_{t-1-32s}
                float bv, br;
                upk2(ring64[bslot * 128 + j], bv, br);
                float nv = (br == rnA) ? bv
                         : __expf(fminf(__logf(bv) + (br - rnA), 85.0f));
                // insert: slot (t-1)&15 becomes (v_{t-1-32s}, v_{t-17-32s})
                {
                    const int is = (p + 15) & 15;             // static
                    w2[is] = pk2(nv, lo2(w2[is]));
                }
                u64 a0 = Z, a1 = Z, a2 = Z, a3 = Z;
                #pragma unroll
                for (int k = 0; k < 16; k += 4) {
                    a0 = ffma2(w2[(p + 15 - k) & 15], dwt2[k + 0], a0);
                    a1 = ffma2(w2[(p + 14 - k) & 15], dwt2[k + 1], a1);
                    a2 = ffma2(w2[(p + 13 - k) & 15], dwt2[k + 2], a2);
                    a3 = ffma2(w2[(p + 12 - k) & 15], dwt2[k + 3], a3);
                }
                float x0, x1, y0, y1, z0, z1, u0, u1;
                upk2(a0, x0, x1); upk2(a1, y0, y1); upk2(a2, z0, z1); upk2(a3, u0, u1);
                pdur[((t + 1) & 1) * 512 + s * 128 + j] =
                    ((x0 + x1) + (y0 + y1)) + ((z0 + z1) + (u0 + u1));
            }
            __syncthreads();                                   // sync2: loop carry
        }
    }

    // ---------- loglik[b] = LSE_j alpha[T-1, j] ----------
    if (tid < 128) {
        float mv = alpha;
        #pragma unroll
        for (int o = 16; o > 0; o >>= 1)
            mv = fmaxf(mv, __shfl_xor_sync(0xffffffffu, mv, o));
        if (lane == 0) fin[w] = mv;
    }
    __syncthreads();
    float m = fmaxf(fmaxf(fin[0], fin[1]), fmaxf(fin[2], fin[3]));
    if (tid < 128) {
        float e = __expf(alpha - m);
        #pragma unroll
        for (int o = 16; o > 0; o >>= 1)
            e += __shfl_xor_sync(0xffffffffu, e, o);
        if (lane == 0) fin[8 + w] = e;
    }
    __syncthreads();
    if (tid == 0) {
        float ssum = (fin[8] + fin[9]) + (fin[10] + fin[11]);
        out[b] = m + __logf(ssum);
    }
}

extern "C" void kernel_launch(void* const* d_in, const int* in_sizes, int n_in,
                              void* d_out, int out_size)
{
    const float* logB = (const float*)d_in[0];
    const float* pi   = (const float*)d_in[1];
    const float* A    = (const float*)d_in[2];
    const float* D    = (const float*)d_in[3];
    float* out = (float*)d_out;

    const size_t smem_bytes = (size_t)SMEM_FLOATS * sizeof(float);  // ~137.1 KB
    cudaFuncSetAttribute(hsmm_fwd_kernel,
                         cudaFuncAttributeMaxDynamicSharedMemorySize,
                         (int)smem_bytes);
    hsmm_fwd_kernel<<<NB, NTHR, smem_bytes>>>(logB, pi, A, D, out);
}

// round 15
// speedup vs baseline: 2.0977x; 2.0977x over previous
#include <cuda_runtime.h>

#define NS   128
#define NT   2048
#define NB   64
#define NTHR 512   // 4 slices (s=tid>>7) x 128 states; tid<128 also combine

// float-index offsets in dynamic smem (R10 layout, frref packed)
#define OFF_RING 0       // 32768: u64 ring[128 slots][128 j] = (v_ins, ref_ins)
#define OFF_PSH  32768   // 256:  [buf][j] exp(alpha - M)
#define OFF_PMAT 33024   // 512:  [s][j] matvec partials
#define OFF_PDUR 33536   // 1024: [buf][s][j] duration tail partials
#define OFF_FRR  34560   // 512:  u64 [buf][j] = (fac, ref_after_step)
#define OFF_WRED 35072   // 8:    [buf][w] per-warp alpha maxes
#define OFF_EFLG 35080   // 2 ints: emergency-rescale generation, by parity
#define OFF_FIN  35084   // 16
#define SMEM_FLOATS 35104  // ~137.1 KB

typedef unsigned long long u64;

__device__ __forceinline__ u64 pk2(float lo, float hi) {
    u64 r;
    asm("mov.b64 %0, {%1, %2};" : "=l"(r)
        : "r"(__float_as_uint(lo)), "r"(__float_as_uint(hi)));
    return r;
}
__device__ __forceinline__ void upk2(u64 v, float& lo, float& hi) {
    unsigned a, b;
    asm("mov.b64 {%0, %1}, %2;" : "=r"(a), "=r"(b) : "l"(v));
    lo = __uint_as_float(a); hi = __uint_as_float(b);
}
__device__ __forceinline__ u64 ffma2(u64 a, u64 b, u64 c) {
    u64 d;
    asm("fma.rn.f32x2 %0, %1, %2, %3;" : "=l"(d) : "l"(a), "l"(b), "l"(c));
    return d;
}
__device__ __forceinline__ unsigned f2key(float x) {
    int i = __float_as_int(x);
    return (unsigned)(i ^ ((i >> 31) | 0x80000000));
}
__device__ __forceinline__ float key2f(unsigned k) {
    int i = ((int)k < 0) ? (int)(k ^ 0x80000000u) : (int)(~k);
    return __int_as_float(i);
}

__global__ __launch_bounds__(NTHR, 1)
void hsmm_fwd_kernel(const float* __restrict__ logB,
                     const float* __restrict__ pi,
                     const float* __restrict__ A,
                     const float* __restrict__ D,
                     float* __restrict__ out)
{
    extern __shared__ float sm[];
    u64*   ring64 = (u64*)(sm + OFF_RING);
    float* p_sh   = sm + OFF_PSH;
    float* pmat   = sm + OFF_PMAT;
    float* pdur   = sm + OFF_PDUR;
    u64*   frref  = (u64*)(sm + OFF_FRR);
    float* wred   = sm + OFF_WRED;
    int*   eflg   = (int*)(sm + OFF_EFLG);
    float* fin    = sm + OFF_FIN;

    const int tid  = threadIdx.x;
    const int b    = blockIdx.x;
    const int lane = tid & 31;
    const int w    = tid >> 5;
    const int j    = tid & 127;
    const int s    = tid >> 7;          // slice 0..3

    // ---------- register tables (R10 shapes: only awt packed) ----------
    u64   awt[16];      // packed exp(A) pairs for matvec slice s
    float dwt[32];      // exp(D) taps, d-1 = 2+32s+k
    float q[32];        // circular window: q[tau & 31] = v_tau
    #pragma unroll
    for (int m = 0; m < 16; ++m) {
        int i0 = 32 * s + 2 * m;
        awt[m] = pk2(__expf(A[i0 * NS + j]), __expf(A[(i0 + 1) * NS + j]));
    }
    #pragma unroll
    for (int k = 0; k < 32; ++k) {
        int c = 2 + 32 * s + k;
        dwt[k] = (c < 128) ? __expf(D[j * 128 + c]) : 0.0f;
        q[k] = 0.0f;
    }

    // ---------- init smem ----------
    for (int lin = tid; lin < 16384; lin += NTHR) ring64[lin] = 0ull;
    for (int lin = tid; lin < 1024;  lin += NTHR) pdur[lin] = 0.0f;
    if (tid < 128) {
        p_sh[tid] = 0.0f;  p_sh[128 + tid] = 0.0f;
        frref[tid] = pk2(1.0f, 0.0f);
        frref[128 + tid] = pk2(1.0f, 0.0f);
    }
    if (tid < 8) wred[tid] = 0.0f;
    if (tid < 2) eflg[tid] = -7;

    // combine-role scalars (tid<128)
    float cum = 0.f, ref = 0.f, v_prev = 0.f, fpend = 1.f, Mprev = 0.f;
    float lb_cur = 0.f, eD0 = 0.f, eD1 = 0.f;
    float dotP = 1.f, baseP = 0.f, vP = 0.f, alpha = 0.f;   // deferred-tail carries
    const float* lbp = logB + (size_t)b * NT * NS + j;
    if (tid < 128) {
        lb_cur = lbp[0];
        eD0 = __expf(D[j * 128 + 0]);
        eD1 = __expf(D[j * 128 + 1]);
    }
    __syncthreads();

    const u64 Z = 0ull;
    for (int tb = 0; tb < NT / 32; ++tb) {
        #pragma unroll
        for (int p = 0; p < 32; ++p) {
            const int t = (tb << 5) + p;

            // ================= Phase A =================
            if (tid < 128 && t > 0) {
                // ---- deferred combine tail of step t-1 (overlaps 16-warp phase A) ----
                alpha = baseP + __logf(dotP);
                const int tm = t - 1;
                bool sched = ((tm & 15) == 15);
                bool emerg = (vP > 1e13f);
                float ins, fac;
                if (emerg | (sched & (vP > 1e-35f))) {
                    float lv = __logf(vP);
                    ref += lv; ins = 1.0f; fac = __expf(-lv);
                    if (emerg & !sched) eflg[tm & 1] = tm;   // benign same-value race
                } else { ins = vP; fac = 1.0f; }
                fpend = fac; v_prev = ins;
                frref[(tm & 1) * 128 + j] = pk2(fac, ref);
                ring64[(tm & 127) * 128 + j] = pk2(ins, ref);
                unsigned ku = f2key(alpha), r;
                asm volatile("redux.sync.max.u32 %0, %1, 0xffffffff;" : "=r"(r) : "r"(ku));
                if (lane == 0) wred[(t & 1) * 4 + w] = key2f(r);
            }
            // trans matvec partial (all threads)
            if (t > 0) {
                const float* psc = p_sh + (t & 1) * 128 + 32 * s;
                u64 a0 = Z, a1 = Z, a2 = Z, a3 = Z;
                #pragma unroll
                for (int k = 0; k < 8; ++k) {
                    ulonglong2 pv = *(const ulonglong2*)(psc + 4 * k);   // broadcast
                    if (k & 1) { a2 = ffma2(pv.x, awt[2 * k], a2); a3 = ffma2(pv.y, awt[2 * k + 1], a3); }
                    else       { a0 = ffma2(pv.x, awt[2 * k], a0); a1 = ffma2(pv.y, awt[2 * k + 1], a1); }
                }
                float x0, x1, y0, y1, z0, z1, u0, u1;
                upk2(a0, x0, x1); upk2(a1, y0, y1); upk2(a2, z0, z1); upk2(a3, u0, u1);
                pmat[s * 128 + j] = ((x0 + x1) + (y0 + y1)) + ((z0 + z1) + (u0 + u1));
            }
            __syncthreads();                                   // sync1

            // ================= Phase B ==================================================
            if (tid < 128) {
                // ---- quick combine chain (loop-critical) ----
                float tl0 = pdur[(t & 1) * 512 +   0 + j];
                float tl1 = pdur[(t & 1) * 512 + 128 + j];
                float tl2 = pdur[(t & 1) * 512 + 256 + j];
                float tl3 = pdur[(t & 1) * 512 + 384 + j];
                float tail = (tl0 + tl1) + (tl2 + tl3);
                float4 wr4 = *(const float4*)(wred + (t & 1) * 4);
                float Mnow = fmaxf(fmaxf(wr4.x, wr4.y), fmaxf(wr4.z, wr4.w));
                float v;
                if (t == 0) {
                    v = __expf(pi[j]);
                } else {
                    float K = __expf(Mprev - cum - ref);
                    float S = (pmat[j] + pmat[128 + j]) + (pmat[256 + j] + pmat[384 + j]);
                    v = S * K;                            // exp(entry_t - cum_t - ref)
                }
                cum += lb_cur;                            // cum[t+1]
                float base = cum + ref;
                float Kp = __expf(fminf(base - Mnow, 85.0f));
                float dot = fmaf(fpend, tail, fmaf(eD1, v_prev, eD0 * v));
                p_sh[((t + 1) & 1) * 128 + j] = dot * Kp; // == exp(alpha_t - Mnow)

                dotP = dot; baseP = base; vP = v;         // defer heavy tail to phase A(t+1)
                Mprev = Mnow;
                lb_cur = lbp[(size_t)((t + 1 < NT) ? t + 1 : t) * NS];
            }

            // ---- dur: 32-tap static circular window in registers (all threads) ----
            {
                float facA, rnA;
                upk2(frref[((t - 1) & 1) * 128 + j], facA, rnA);
                if (t > 0) {
                    bool rs = ((((t - 1) & 15) == 15) || (eflg[(t - 1) & 1] == t - 1));
                    if (rs) {
                        #pragma unroll
                        for (int k = 0; k < 32; ++k) q[k] *= facA;
                    }
                }
                const int bslot = (t - 1 - 32 * s) & 127;     // v_{t-1-32s}
                float bv, br;
                upk2(ring64[bslot * 128 + j], bv, br);
                float nv = (br == rnA) ? bv
                         : __expf(fminf(__logf(bv) + (br - rnA), 85.0f));
                q[(p + 31) & 31] = nv;                        // q[(t-1) & 31], static index

                float c0 = 0.f, c1 = 0.f, c2 = 0.f, c3 = 0.f;
                #pragma unroll
                for (int k = 0; k < 32; k += 4) {
                    c0 = fmaf(q[(p + 31 - k) & 31], dwt[k + 0], c0);
                    c1 = fmaf(q[(p + 30 - k) & 31], dwt[k + 1], c1);
                    c2 = fmaf(q[(p + 29 - k) & 31], dwt[k + 2], c2);
                    c3 = fmaf(q[(p + 28 - k) & 31], dwt[k + 3], c3);
                }
                pdur[((t + 1) & 1) * 512 + s * 128 + j] = (c0 + c1) + (c2 + c3);
            }
            __syncthreads();                                   // sync2: loop carry
        }
    }

    // ---------- final deferred tail (t = NT-1) + loglik ----------
    if (tid < 128) alpha = baseP + __logf(dotP);
    if (tid < 128) {
        float mv = alpha;
        #pragma unroll
        for (int o = 16; o > 0; o >>= 1)
            mv = fmaxf(mv, __shfl_xor_sync(0xffffffffu, mv, o));
        if (lane == 0) fin[w] = mv;
    }
    __syncthreads();
    float m = fmaxf(fmaxf(fin[0], fin[1]), fmaxf(fin[2], fin[3]));
    if (tid < 128) {
        float e = __expf(alpha - m);
        #pragma unroll
        for (int o = 16; o > 0; o >>= 1)
            e += __shfl_xor_sync(0xffffffffu, e, o);
        if (lane == 0) fin[8 + w] = e;
    }
    __syncthreads();
    if (tid == 0) {
        float ssum = (fin[8] + fin[9]) + (fin[10] + fin[11]);
        out[b] = m + __logf(ssum);
    }
}

extern "C" void kernel_launch(void* const* d_in, const int* in_sizes, int n_in,
                              void* d_out, int out_size)
{
    const float* logB = (const float*)d_in[0];
    const float* pi   = (const float*)d_in[1];
    const float* A    = (const float*)d_in[2];
    const float* D    = (const float*)d_in[3];
    float* out = (float*)d_out;

    const size_t smem_bytes = (size_t)SMEM_FLOATS * sizeof(float);  // ~137.1 KB
    cudaFuncSetAttribute(hsmm_fwd_kernel,
                         cudaFuncAttributeMaxDynamicSharedMemorySize,
                         (int)smem_bytes);
    hsmm_fwd_kernel<<<NB, NTHR, smem_bytes>>>(logB, pi, A, D, out);
}